// round 1
// baseline (speedup 1.0000x reference)
#include <cuda_runtime.h>

#define B_ 4096
#define N_ 64
#define H_ 256

// Scratch (allocation-free rule: __device__ globals)
__device__ float g_UV[N_ * H_];     //  64 KiB
__device__ float g_HW[N_ * H_];     //  64 KiB
__device__ float g_sW[B_ * H_];     //   4 MiB
__device__ float g_gate[B_ * N_];   //   1 MiB

// ---------------------------------------------------------------------------
// Kernel 1: UV[n,k] = sum_h h[n,h]*U[k,h] + w[n,h]*V[k,h];  HW[n,h] = h+w
// grid = 64 (one block per n), block = 256 (one thread per k)
// ---------------------------------------------------------------------------
__global__ void __launch_bounds__(256) k1_uv(
    const float* __restrict__ h, const float* __restrict__ w,
    const float* __restrict__ U, const float* __restrict__ V)
{
    __shared__ float hs[H_], ws[H_];
    const int n = blockIdx.x;
    const int k = threadIdx.x;
    float hv = h[n * H_ + k];
    float wv = w[n * H_ + k];
    hs[k] = hv;
    ws[k] = wv;
    g_HW[n * H_ + k] = hv + wv;
    __syncthreads();

    const float4* u4 = (const float4*)(U + k * H_);
    const float4* v4 = (const float4*)(V + k * H_);
    float acc = 0.f;
#pragma unroll 8
    for (int i = 0; i < H_ / 4; ++i) {
        float4 u = u4[i];
        float4 v = v4[i];
        acc = fmaf(hs[4 * i + 0], u.x, acc);
        acc = fmaf(hs[4 * i + 1], u.y, acc);
        acc = fmaf(hs[4 * i + 2], u.z, acc);
        acc = fmaf(hs[4 * i + 3], u.w, acc);
        acc = fmaf(ws[4 * i + 0], v.x, acc);
        acc = fmaf(ws[4 * i + 1], v.y, acc);
        acc = fmaf(ws[4 * i + 2], v.z, acc);
        acc = fmaf(ws[4 * i + 3], v.w, acc);
    }
    g_UV[n * H_ + k] = acc;
}

// ---------------------------------------------------------------------------
// Kernel 2: fused GEMM  C[b,m] = s_t[b,:] . M[m,:],  M = concat(W_w, HW)
//   m <  256 -> g_sW[b,m]
//   m >= 256 -> g_gate[b,m-256] = sigmoid(C)
// M = 4096, N2 = 320, K = 256. 64x64 tiles, Kc = 32, 256 threads, 4x4 micro.
// grid = (5 m-tiles, 64 b-tiles)
// ---------------------------------------------------------------------------
__global__ void __launch_bounds__(256) k2_gemm(
    const float* __restrict__ s, const float* __restrict__ W)
{
    __shared__ float sa[64][33];  // [b_local][k], padded
    __shared__ float sb[64][33];  // [m_local][k], padded

    const int tid = threadIdx.x;
    const int tx = tid & 15;          // 0..15 -> m micro
    const int ty = tid >> 4;          // 0..15 -> b micro
    const int m0 = blockIdx.x * 64;   // 0,64,128,192,256
    const int b0 = blockIdx.y * 64;
    // tiles never straddle the 256 boundary (64 | 256)
    const float* wbase = (blockIdx.x < 4) ? (W + m0 * H_) : g_HW;

    const int lr = tid >> 3;          // 0..31 load row
    const int lc = (tid & 7) << 2;    // 0,4,...,28 load col (float4)

    float acc[4][4] = {};

    for (int kc = 0; kc < H_; kc += 32) {
        float4 a0 = *(const float4*)&s[(b0 + lr) * H_ + kc + lc];
        float4 a1 = *(const float4*)&s[(b0 + lr + 32) * H_ + kc + lc];
        float4 w0 = *(const float4*)&wbase[lr * H_ + kc + lc];
        float4 w1 = *(const float4*)&wbase[(lr + 32) * H_ + kc + lc];
        sa[lr][lc + 0] = a0.x; sa[lr][lc + 1] = a0.y; sa[lr][lc + 2] = a0.z; sa[lr][lc + 3] = a0.w;
        sa[lr + 32][lc + 0] = a1.x; sa[lr + 32][lc + 1] = a1.y; sa[lr + 32][lc + 2] = a1.z; sa[lr + 32][lc + 3] = a1.w;
        sb[lr][lc + 0] = w0.x; sb[lr][lc + 1] = w0.y; sb[lr][lc + 2] = w0.z; sb[lr][lc + 3] = w0.w;
        sb[lr + 32][lc + 0] = w1.x; sb[lr + 32][lc + 1] = w1.y; sb[lr + 32][lc + 2] = w1.z; sb[lr + 32][lc + 3] = w1.w;
        __syncthreads();

#pragma unroll 8
        for (int k = 0; k < 32; ++k) {
            float av[4], bv[4];
#pragma unroll
            for (int i = 0; i < 4; ++i) av[i] = sa[ty * 4 + i][k];
#pragma unroll
            for (int j = 0; j < 4; ++j) bv[j] = sb[tx * 4 + j][k];
#pragma unroll
            for (int i = 0; i < 4; ++i)
#pragma unroll
                for (int j = 0; j < 4; ++j)
                    acc[i][j] = fmaf(av[i], bv[j], acc[i][j]);
        }
        __syncthreads();
    }

    if (blockIdx.x < 4) {
#pragma unroll
        for (int i = 0; i < 4; ++i) {
            int b = b0 + ty * 4 + i;
#pragma unroll
            for (int j = 0; j < 4; ++j) {
                int m = m0 + tx * 4 + j;
                g_sW[b * H_ + m] = acc[i][j];
            }
        }
    } else {
#pragma unroll
        for (int i = 0; i < 4; ++i) {
            int b = b0 + ty * 4 + i;
#pragma unroll
            for (int j = 0; j < 4; ++j) {
                int m = tx * 4 + j;  // gate index 0..63
                g_gate[b * N_ + m] = 1.0f / (1.0f + __expf(-acc[i][j]));
            }
        }
    }
}

// ---------------------------------------------------------------------------
// Kernel 3: out[b,n,:] = normalize( h[n,:] + g[b,n]*prelu(UV[n,:] + sW[b,:]) )
// One warp per (b,n) row: 8 elems/lane, norm = warp shuffle reduction.
// UV/h register-cached per thread. No shared memory, no block barriers.
// grid = (4 n-tiles of 16, B/TB), block = 256 (8 warps; warp w -> rows w, w+8)
// ---------------------------------------------------------------------------
__device__ __forceinline__ void row_step(const float4 uv, const float4 hh,
                                         const float4 sw, const float g,
                                         const float a, float4& o, float& ss)
{
    float c, t;
    c = uv.x + sw.x; c = (c >= 0.f) ? c : a * c; t = fmaf(g, c, hh.x); o.x = t; ss = fmaf(t, t, ss);
    c = uv.y + sw.y; c = (c >= 0.f) ? c : a * c; t = fmaf(g, c, hh.y); o.y = t; ss = fmaf(t, t, ss);
    c = uv.z + sw.z; c = (c >= 0.f) ? c : a * c; t = fmaf(g, c, hh.z); o.z = t; ss = fmaf(t, t, ss);
    c = uv.w + sw.w; c = (c >= 0.f) ? c : a * c; t = fmaf(g, c, hh.w); o.w = t; ss = fmaf(t, t, ss);
}

__global__ void __launch_bounds__(256) k3_main(
    const float* __restrict__ h, const float* __restrict__ a_ptr,
    float* __restrict__ out, const int tb)
{
    const int warp = threadIdx.x >> 5;
    const int lane = threadIdx.x & 31;
    const int n0 = blockIdx.x * 16;
    const int b_begin = blockIdx.y * tb;
    const float a = __ldg(a_ptr);

    const int nA = n0 + warp;        // row handled in slot A
    const int nB = n0 + warp + 8;    // row handled in slot B
    const int kb = lane * 8;         // this lane's k range: kb..kb+7

    // Register-cache UV and h slices for both rows (loaded once).
    const float4* p;
    p = (const float4*)&g_UV[nA * H_ + kb]; float4 uvA0 = p[0], uvA1 = p[1];
    p = (const float4*)&g_UV[nB * H_ + kb]; float4 uvB0 = p[0], uvB1 = p[1];
    p = (const float4*)&h[nA * H_ + kb];    float4 hA0 = p[0], hA1 = p[1];
    p = (const float4*)&h[nB * H_ + kb];    float4 hB0 = p[0], hB1 = p[1];

    for (int b = b_begin; b < b_begin + tb; ++b) {
        const float4* swp = (const float4*)&g_sW[b * H_ + kb];
        const float4 s0 = __ldg(swp);
        const float4 s1 = __ldg(swp + 1);
        const float gA = __ldg(&g_gate[b * N_ + nA]);
        const float gB = __ldg(&g_gate[b * N_ + nB]);

        float4 oA0, oA1, oB0, oB1;
        float ssA = 0.f, ssB = 0.f;
        row_step(uvA0, hA0, s0, gA, a, oA0, ssA);
        row_step(uvA1, hA1, s1, gA, a, oA1, ssA);
        row_step(uvB0, hB0, s0, gB, a, oB0, ssB);
        row_step(uvB1, hB1, s1, gB, a, oB1, ssB);

#pragma unroll
        for (int off = 16; off > 0; off >>= 1) {
            ssA += __shfl_xor_sync(0xFFFFFFFFu, ssA, off);
            ssB += __shfl_xor_sync(0xFFFFFFFFu, ssB, off);
        }
        const float iA = rsqrtf(ssA);
        const float iB = rsqrtf(ssB);

        float4* oA = (float4*)&out[((size_t)b * N_ + nA) * H_ + kb];
        float4* oB = (float4*)&out[((size_t)b * N_ + nB) * H_ + kb];
        oA[0] = make_float4(oA0.x * iA, oA0.y * iA, oA0.z * iA, oA0.w * iA);
        oA[1] = make_float4(oA1.x * iA, oA1.y * iA, oA1.z * iA, oA1.w * iA);
        oB[0] = make_float4(oB0.x * iB, oB0.y * iB, oB0.z * iB, oB0.w * iB);
        oB[1] = make_float4(oB1.x * iB, oB1.y * iB, oB1.z * iB, oB1.w * iB);
    }
}

// ---------------------------------------------------------------------------
extern "C" void kernel_launch(void* const* d_in, const int* in_sizes, int n_in,
                              void* d_out, int out_size)
{
    const float* s_t = (const float*)d_in[0];   // [B,H]
    const float* h   = (const float*)d_in[1];   // [1,N,H]
    const float* w   = (const float*)d_in[2];   // [1,N,H]
    const float* U   = (const float*)d_in[3];   // [H,H]
    const float* V   = (const float*)d_in[4];   // [H,H]
    const float* W   = (const float*)d_in[5];   // [H,H]
    const float* pa  = (const float*)d_in[6];   // [1]
    float* out = (float*)d_out;                 // [B,N,H]

    k1_uv<<<N_, H_>>>(h, w, U, V);

    dim3 g2(5, B_ / 64);
    k2_gemm<<<g2, 256>>>(s_t, W);

    const int TB = 8;
    dim3 g3(N_ / 16, B_ / TB);
    k3_main<<<g3, 256>>>(h, pa, out, TB);
}

// round 2
// speedup vs baseline: 1.3872x; 1.3872x over previous
#include <cuda_runtime.h>

#define B_ 4096
#define N_ 64
#define H_ 256
#define TB3 16

// Scratch (allocation-free rule: __device__ globals)
__device__ float g_UV[N_ * H_];     //  64 KiB
__device__ float g_sW[B_ * H_];     //   4 MiB
__device__ float g_gate[B_ * N_];   //   1 MiB

// ---------------------------------------------------------------------------
// Merged kernel 1+2 (independent work, one grid so they overlap):
//  blocks [0,320):    GEMM  C[b,m] = s_t[b,:] . M[m,:], M = concat(W_w, h+w)
//                       m<256 -> g_sW ; m>=256 -> g_gate = sigmoid(C)
//  blocks [320,2368): UV[n,k] = sum_h h[n,h]*U[k,h] + w[n,h]*V[k,h]
//                       warp per (n,k) output, shuffle reduction
// ---------------------------------------------------------------------------
__global__ void __launch_bounds__(256) k12(
    const float* __restrict__ s, const float* __restrict__ W,
    const float* __restrict__ h, const float* __restrict__ w,
    const float* __restrict__ U, const float* __restrict__ V)
{
    __shared__ float sa[64][33];
    __shared__ float sb[64][33];
    const int tid = threadIdx.x;
    const int blk = blockIdx.x;

    if (blk < 320) {
        // ---------------- GEMM part ----------------
        const int mx = blk % 5;
        const int b0 = (blk / 5) * 64;
        const int m0 = mx * 64;
        const bool gate_tile = (mx == 4);
        const int tx = tid & 15;
        const int ty = tid >> 4;
        const int lr = tid >> 3;
        const int lc = (tid & 7) << 2;

        float acc[4][4] = {};

        for (int kc = 0; kc < H_; kc += 32) {
            float4 a0 = *(const float4*)&s[(b0 + lr) * H_ + kc + lc];
            float4 a1 = *(const float4*)&s[(b0 + lr + 32) * H_ + kc + lc];
            float4 w0, w1;
            if (!gate_tile) {
                w0 = *(const float4*)&W[(m0 + lr) * H_ + kc + lc];
                w1 = *(const float4*)&W[(m0 + lr + 32) * H_ + kc + lc];
            } else {
                float4 h0 = *(const float4*)&h[lr * H_ + kc + lc];
                float4 h1 = *(const float4*)&h[(lr + 32) * H_ + kc + lc];
                float4 q0 = *(const float4*)&w[lr * H_ + kc + lc];
                float4 q1 = *(const float4*)&w[(lr + 32) * H_ + kc + lc];
                w0 = make_float4(h0.x + q0.x, h0.y + q0.y, h0.z + q0.z, h0.w + q0.w);
                w1 = make_float4(h1.x + q1.x, h1.y + q1.y, h1.z + q1.z, h1.w + q1.w);
            }
            sa[lr][lc + 0] = a0.x; sa[lr][lc + 1] = a0.y; sa[lr][lc + 2] = a0.z; sa[lr][lc + 3] = a0.w;
            sa[lr + 32][lc + 0] = a1.x; sa[lr + 32][lc + 1] = a1.y; sa[lr + 32][lc + 2] = a1.z; sa[lr + 32][lc + 3] = a1.w;
            sb[lr][lc + 0] = w0.x; sb[lr][lc + 1] = w0.y; sb[lr][lc + 2] = w0.z; sb[lr][lc + 3] = w0.w;
            sb[lr + 32][lc + 0] = w1.x; sb[lr + 32][lc + 1] = w1.y; sb[lr + 32][lc + 2] = w1.z; sb[lr + 32][lc + 3] = w1.w;
            __syncthreads();

#pragma unroll 8
            for (int k = 0; k < 32; ++k) {
                float av[4], bv[4];
#pragma unroll
                for (int i = 0; i < 4; ++i) av[i] = sa[ty * 4 + i][k];
#pragma unroll
                for (int j = 0; j < 4; ++j) bv[j] = sb[tx * 4 + j][k];
#pragma unroll
                for (int i = 0; i < 4; ++i)
#pragma unroll
                    for (int j = 0; j < 4; ++j)
                        acc[i][j] = fmaf(av[i], bv[j], acc[i][j]);
            }
            __syncthreads();
        }

        if (!gate_tile) {
#pragma unroll
            for (int i = 0; i < 4; ++i) {
                int b = b0 + ty * 4 + i;
#pragma unroll
                for (int j = 0; j < 4; ++j)
                    g_sW[b * H_ + m0 + tx * 4 + j] = acc[i][j];
            }
        } else {
#pragma unroll
            for (int i = 0; i < 4; ++i) {
                int b = b0 + ty * 4 + i;
#pragma unroll
                for (int j = 0; j < 4; ++j)
                    g_gate[b * N_ + tx * 4 + j] = 1.0f / (1.0f + __expf(-acc[i][j]));
            }
        }
    } else {
        // ---------------- UV part: warp per output element ----------------
        const int id = blk - 320;        // 0..2047
        const int n = id >> 5;           // 0..63
        const int kg = id & 31;          // 0..31
        const int warp = tid >> 5;
        const int lane = tid & 31;
        const int k = kg * 8 + warp;     // 0..255
        const int off = lane * 8;

        const float4* u4 = (const float4*)(U + k * H_ + off);
        const float4* v4 = (const float4*)(V + k * H_ + off);
        const float4* h4 = (const float4*)(h + n * H_ + off);
        const float4* w4 = (const float4*)(w + n * H_ + off);
        float4 u0 = u4[0], u1 = u4[1];
        float4 v0 = v4[0], v1 = v4[1];
        float4 x0 = __ldg(h4), x1 = __ldg(h4 + 1);
        float4 y0 = __ldg(w4), y1 = __ldg(w4 + 1);

        float acc = 0.f;
        acc = fmaf(u0.x, x0.x, acc); acc = fmaf(u0.y, x0.y, acc);
        acc = fmaf(u0.z, x0.z, acc); acc = fmaf(u0.w, x0.w, acc);
        acc = fmaf(u1.x, x1.x, acc); acc = fmaf(u1.y, x1.y, acc);
        acc = fmaf(u1.z, x1.z, acc); acc = fmaf(u1.w, x1.w, acc);
        acc = fmaf(v0.x, y0.x, acc); acc = fmaf(v0.y, y0.y, acc);
        acc = fmaf(v0.z, y0.z, acc); acc = fmaf(v0.w, y0.w, acc);
        acc = fmaf(v1.x, y1.x, acc); acc = fmaf(v1.y, y1.y, acc);
        acc = fmaf(v1.z, y1.z, acc); acc = fmaf(v1.w, y1.w, acc);

#pragma unroll
        for (int offm = 16; offm > 0; offm >>= 1)
            acc += __shfl_xor_sync(0xFFFFFFFFu, acc, offm);
        if (lane == 0) g_UV[n * H_ + k] = acc;
    }
}

// ---------------------------------------------------------------------------
// Kernel 3: out[b,n,:] = normalize( h[n,:] + g[b,n]*prelu(UV[n,:] + sW[b,:]) )
// One warp per (b,n) row pair; UV/h register-cached; sW+gate staged to smem
// once per block per b (double-buffered prefetch). Lane layout:
//   slice0 = k in [lane*4, lane*4+4), slice1 = k in [128+lane*4, 128+lane*4+4)
// -> conflict-free float4 smem reads and fully coalesced 512B stores.
// grid = (4 n-tiles, B/TB3), block = 256 (8 warps; warp w -> rows w, w+8)
// ---------------------------------------------------------------------------
__device__ __forceinline__ void row_step(const float4 uv, const float4 hh,
                                         const float4 sw, const float g,
                                         const float a, float4& o, float& ss)
{
    float c, t;
    c = uv.x + sw.x; c = (c >= 0.f) ? c : a * c; t = fmaf(g, c, hh.x); o.x = t; ss = fmaf(t, t, ss);
    c = uv.y + sw.y; c = (c >= 0.f) ? c : a * c; t = fmaf(g, c, hh.y); o.y = t; ss = fmaf(t, t, ss);
    c = uv.z + sw.z; c = (c >= 0.f) ? c : a * c; t = fmaf(g, c, hh.z); o.z = t; ss = fmaf(t, t, ss);
    c = uv.w + sw.w; c = (c >= 0.f) ? c : a * c; t = fmaf(g, c, hh.w); o.w = t; ss = fmaf(t, t, ss);
}

__global__ void __launch_bounds__(256) k3_main(
    const float* __restrict__ h, const float* __restrict__ a_ptr,
    float* __restrict__ out)
{
    __shared__ float4 sw[2][64];
    __shared__ float gt[2][16];

    const int tid = threadIdx.x;
    const int warp = tid >> 5;
    const int lane = tid & 31;
    const int n0 = blockIdx.x * 16;
    const int b0 = blockIdx.y * TB3;
    const float a = __ldg(a_ptr);

    const int nA = n0 + warp;
    const int nB = n0 + warp + 8;
    const int k0 = lane * 4;
    const int k1 = 128 + lane * 4;

    // Register-cache UV and h slices for both rows (loaded once per block).
    float4 uvA0 = *(const float4*)&g_UV[nA * H_ + k0];
    float4 uvA1 = *(const float4*)&g_UV[nA * H_ + k1];
    float4 uvB0 = *(const float4*)&g_UV[nB * H_ + k0];
    float4 uvB1 = *(const float4*)&g_UV[nB * H_ + k1];
    float4 hA0 = __ldg((const float4*)&h[nA * H_ + k0]);
    float4 hA1 = __ldg((const float4*)&h[nA * H_ + k1]);
    float4 hB0 = __ldg((const float4*)&h[nB * H_ + k0]);
    float4 hB1 = __ldg((const float4*)&h[nB * H_ + k1]);

    // Prologue stage of b0
    if (tid < 64) sw[0][tid] = __ldg((const float4*)&g_sW[(size_t)b0 * H_] + tid);
    else if (tid < 80) gt[0][tid - 64] = __ldg(&g_gate[b0 * N_ + n0 + (tid - 64)]);
    __syncthreads();

    for (int i = 0; i < TB3; ++i) {
        const int buf = i & 1;
        // Prefetch next b into the other buffer (overlaps with compute below)
        if (i + 1 < TB3) {
            const int bn = b0 + i + 1;
            if (tid < 64) sw[buf ^ 1][tid] = __ldg((const float4*)&g_sW[(size_t)bn * H_] + tid);
            else if (tid < 80) gt[buf ^ 1][tid - 64] = __ldg(&g_gate[bn * N_ + n0 + (tid - 64)]);
        }

        const float4 s0 = sw[buf][lane];        // conflict-free
        const float4 s1 = sw[buf][lane + 32];
        const float gA = gt[buf][warp];
        const float gB = gt[buf][warp + 8];

        float4 oA0, oA1, oB0, oB1;
        float ssA = 0.f, ssB = 0.f;
        row_step(uvA0, hA0, s0, gA, a, oA0, ssA);
        row_step(uvA1, hA1, s1, gA, a, oA1, ssA);
        row_step(uvB0, hB0, s0, gB, a, oB0, ssB);
        row_step(uvB1, hB1, s1, gB, a, oB1, ssB);

#pragma unroll
        for (int offm = 16; offm > 0; offm >>= 1) {
            ssA += __shfl_xor_sync(0xFFFFFFFFu, ssA, offm);
            ssB += __shfl_xor_sync(0xFFFFFFFFu, ssB, offm);
        }
        const float iA = rsqrtf(ssA);
        const float iB = rsqrtf(ssB);

        const int b = b0 + i;
        float4* oA = (float4*)&out[((size_t)b * N_ + nA) * H_];
        float4* oB = (float4*)&out[((size_t)b * N_ + nB) * H_];
        oA[lane]      = make_float4(oA0.x * iA, oA0.y * iA, oA0.z * iA, oA0.w * iA);
        oA[32 + lane] = make_float4(oA1.x * iA, oA1.y * iA, oA1.z * iA, oA1.w * iA);
        oB[lane]      = make_float4(oB0.x * iB, oB0.y * iB, oB0.z * iB, oB0.w * iB);
        oB[32 + lane] = make_float4(oB1.x * iB, oB1.y * iB, oB1.z * iB, oB1.w * iB);

        __syncthreads();
    }
}

// ---------------------------------------------------------------------------
extern "C" void kernel_launch(void* const* d_in, const int* in_sizes, int n_in,
                              void* d_out, int out_size)
{
    const float* s_t = (const float*)d_in[0];   // [B,H]
    const float* h   = (const float*)d_in[1];   // [1,N,H]
    const float* w   = (const float*)d_in[2];   // [1,N,H]
    const float* U   = (const float*)d_in[3];   // [H,H]
    const float* V   = (const float*)d_in[4];   // [H,H]
    const float* W   = (const float*)d_in[5];   // [H,H]
    const float* pa  = (const float*)d_in[6];   // [1]
    float* out = (float*)d_out;                 // [B,N,H]

    k12<<<320 + 2048, 256>>>(s_t, W, h, w, U, V);

    dim3 g3(N_ / 16, B_ / TB3);
    k3_main<<<g3, 256>>>(h, pa, out);
}

// round 3
// speedup vs baseline: 1.4942x; 1.0772x over previous
#include <cuda_runtime.h>

#define B_ 4096
#define N_ 64
#define H_ 256
#define TB3 16

typedef unsigned long long u64;

// Scratch (allocation-free rule: __device__ globals)
__device__ float g_UV[N_ * H_];     //  64 KiB
__device__ float g_sW[B_ * H_];     //   4 MiB
__device__ float g_gate[B_ * N_];   //   1 MiB

// ---------- packed fp32x2 helpers (sm_103a FFMA2) ----------
__device__ __forceinline__ u64 pack2(float x, float y) {
    u64 r; asm("mov.b64 %0, {%1, %2};" : "=l"(r) : "f"(x), "f"(y)); return r;
}
__device__ __forceinline__ u64 fma2(u64 a, u64 b, u64 c) {
    u64 d; asm("fma.rn.f32x2 %0, %1, %2, %3;" : "=l"(d) : "l"(a), "l"(b), "l"(c)); return d;
}
__device__ __forceinline__ float2 unpack2(u64 v) {
    float2 r; asm("mov.b64 {%0, %1}, %2;" : "=f"(r.x), "=f"(r.y) : "l"(v)); return r;
}

// ---------------------------------------------------------------------------
// Merged kernel 1+2:
//  blocks [0,320):    GEMM  C[b,m] = s_t[b,:] . M[m,:], M = concat(W_w, h+w)
//    64b x 64m tiles, Kc=32, k-major smem, 4x4 micro via f32x2 packed FMA.
//    m<256 -> g_sW ; m>=256 (gate tile) -> g_gate = sigmoid(C)
//  blocks [320,2368): UV[n,k] = sum_h h[n,h]*U[k,h] + w[n,h]*V[k,h]
// ---------------------------------------------------------------------------
__global__ void __launch_bounds__(256) k12(
    const float* __restrict__ s, const float* __restrict__ W,
    const float* __restrict__ h, const float* __restrict__ w,
    const float* __restrict__ U, const float* __restrict__ V)
{
    __shared__ float sa[32][64];   // [k][b_local]
    __shared__ float sb[32][64];   // [k][m_local]
    const int tid = threadIdx.x;
    const int blk = blockIdx.x;

    if (blk < 320) {
        const int mx = blk % 5;
        const int b0 = (blk / 5) * 64;
        const int m0 = mx * 64;
        const bool gate_tile = (mx == 4);

        const int row = tid & 63;          // load row
        const int kq = (tid >> 6) << 2;    // 0,4,8,12
        const int ty = tid >> 4;           // 0..15 -> b micro quad
        const int tx = tid & 15;           // 0..15 -> m micro quad
        const int rb = ty << 2;
        const int cm = tx << 2;

        u64 acc2[2][4] = {};

        // prologue: stage kc=0 into registers
        float4 ra0, ra1, rb0, rb1;
        {
            ra0 = *(const float4*)&s[(b0 + row) * H_ + kq];
            ra1 = *(const float4*)&s[(b0 + row) * H_ + 16 + kq];
            if (!gate_tile) {
                rb0 = *(const float4*)&W[(m0 + row) * H_ + kq];
                rb1 = *(const float4*)&W[(m0 + row) * H_ + 16 + kq];
            } else {
                float4 x0 = *(const float4*)&h[row * H_ + kq];
                float4 x1 = *(const float4*)&h[row * H_ + 16 + kq];
                float4 y0 = *(const float4*)&w[row * H_ + kq];
                float4 y1 = *(const float4*)&w[row * H_ + 16 + kq];
                rb0 = make_float4(x0.x + y0.x, x0.y + y0.y, x0.z + y0.z, x0.w + y0.w);
                rb1 = make_float4(x1.x + y1.x, x1.y + y1.y, x1.z + y1.z, x1.w + y1.w);
            }
        }

        for (int kc = 0; kc < H_; kc += 32) {
            // transpose-store staged regs into k-major smem
            sa[kq + 0][row] = ra0.x; sa[kq + 1][row] = ra0.y;
            sa[kq + 2][row] = ra0.z; sa[kq + 3][row] = ra0.w;
            sa[16 + kq + 0][row] = ra1.x; sa[16 + kq + 1][row] = ra1.y;
            sa[16 + kq + 2][row] = ra1.z; sa[16 + kq + 3][row] = ra1.w;
            sb[kq + 0][row] = rb0.x; sb[kq + 1][row] = rb0.y;
            sb[kq + 2][row] = rb0.z; sb[kq + 3][row] = rb0.w;
            sb[16 + kq + 0][row] = rb1.x; sb[16 + kq + 1][row] = rb1.y;
            sb[16 + kq + 2][row] = rb1.z; sb[16 + kq + 3][row] = rb1.w;
            __syncthreads();

            // prefetch next kc (overlaps with compute)
            if (kc + 32 < H_) {
                const int kn = kc + 32;
                ra0 = *(const float4*)&s[(b0 + row) * H_ + kn + kq];
                ra1 = *(const float4*)&s[(b0 + row) * H_ + kn + 16 + kq];
                if (!gate_tile) {
                    rb0 = *(const float4*)&W[(m0 + row) * H_ + kn + kq];
                    rb1 = *(const float4*)&W[(m0 + row) * H_ + kn + 16 + kq];
                } else {
                    float4 x0 = *(const float4*)&h[row * H_ + kn + kq];
                    float4 x1 = *(const float4*)&h[row * H_ + kn + 16 + kq];
                    float4 y0 = *(const float4*)&w[row * H_ + kn + kq];
                    float4 y1 = *(const float4*)&w[row * H_ + kn + 16 + kq];
                    rb0 = make_float4(x0.x + y0.x, x0.y + y0.y, x0.z + y0.z, x0.w + y0.w);
                    rb1 = make_float4(x1.x + y1.x, x1.y + y1.y, x1.z + y1.z, x1.w + y1.w);
                }
            }

#pragma unroll 8
            for (int k = 0; k < 32; ++k) {
                const ulonglong2 a2 = *(const ulonglong2*)&sa[k][rb];  // b pairs, natural
                const float4 bv = *(const float4*)&sb[k][cm];
                u64 bx = pack2(bv.x, bv.x);
                u64 by = pack2(bv.y, bv.y);
                u64 bz = pack2(bv.z, bv.z);
                u64 bw = pack2(bv.w, bv.w);
                acc2[0][0] = fma2(a2.x, bx, acc2[0][0]);
                acc2[0][1] = fma2(a2.x, by, acc2[0][1]);
                acc2[0][2] = fma2(a2.x, bz, acc2[0][2]);
                acc2[0][3] = fma2(a2.x, bw, acc2[0][3]);
                acc2[1][0] = fma2(a2.y, bx, acc2[1][0]);
                acc2[1][1] = fma2(a2.y, by, acc2[1][1]);
                acc2[1][2] = fma2(a2.y, bz, acc2[1][2]);
                acc2[1][3] = fma2(a2.y, bw, acc2[1][3]);
            }
            __syncthreads();
        }

        // unpack: acc2[ib][j] -> rows rb+2*ib(+1), col cm+j
#pragma unroll
        for (int ib = 0; ib < 2; ++ib) {
            float2 c0 = unpack2(acc2[ib][0]);
            float2 c1 = unpack2(acc2[ib][1]);
            float2 c2 = unpack2(acc2[ib][2]);
            float2 c3 = unpack2(acc2[ib][3]);
            const int bA = b0 + rb + 2 * ib;
            if (!gate_tile) {
                *(float4*)&g_sW[bA * H_ + m0 + cm] = make_float4(c0.x, c1.x, c2.x, c3.x);
                *(float4*)&g_sW[(bA + 1) * H_ + m0 + cm] = make_float4(c0.y, c1.y, c2.y, c3.y);
            } else {
                float4 g0 = make_float4(1.0f / (1.0f + __expf(-c0.x)),
                                        1.0f / (1.0f + __expf(-c1.x)),
                                        1.0f / (1.0f + __expf(-c2.x)),
                                        1.0f / (1.0f + __expf(-c3.x)));
                float4 g1 = make_float4(1.0f / (1.0f + __expf(-c0.y)),
                                        1.0f / (1.0f + __expf(-c1.y)),
                                        1.0f / (1.0f + __expf(-c2.y)),
                                        1.0f / (1.0f + __expf(-c3.y)));
                *(float4*)&g_gate[bA * N_ + cm] = g0;
                *(float4*)&g_gate[(bA + 1) * N_ + cm] = g1;
            }
        }
    } else {
        // ---------------- UV part: warp per output element ----------------
        const int id = blk - 320;
        const int n = id >> 5;
        const int kg = id & 31;
        const int warp = tid >> 5;
        const int lane = tid & 31;
        const int k = kg * 8 + warp;
        const int off = lane * 8;

        const float4* u4 = (const float4*)(U + k * H_ + off);
        const float4* v4 = (const float4*)(V + k * H_ + off);
        const float4* h4 = (const float4*)(h + n * H_ + off);
        const float4* w4 = (const float4*)(w + n * H_ + off);
        float4 u0 = u4[0], u1 = u4[1];
        float4 v0 = v4[0], v1 = v4[1];
        float4 x0 = __ldg(h4), x1 = __ldg(h4 + 1);
        float4 y0 = __ldg(w4), y1 = __ldg(w4 + 1);

        float acc = 0.f;
        acc = fmaf(u0.x, x0.x, acc); acc = fmaf(u0.y, x0.y, acc);
        acc = fmaf(u0.z, x0.z, acc); acc = fmaf(u0.w, x0.w, acc);
        acc = fmaf(u1.x, x1.x, acc); acc = fmaf(u1.y, x1.y, acc);
        acc = fmaf(u1.z, x1.z, acc); acc = fmaf(u1.w, x1.w, acc);
        acc = fmaf(v0.x, y0.x, acc); acc = fmaf(v0.y, y0.y, acc);
        acc = fmaf(v0.z, y0.z, acc); acc = fmaf(v0.w, y0.w, acc);
        acc = fmaf(v1.x, y1.x, acc); acc = fmaf(v1.y, y1.y, acc);
        acc = fmaf(v1.z, y1.z, acc); acc = fmaf(v1.w, y1.w, acc);

#pragma unroll
        for (int offm = 16; offm > 0; offm >>= 1)
            acc += __shfl_xor_sync(0xFFFFFFFFu, acc, offm);
        if (lane == 0) g_UV[n * H_ + k] = acc;
    }
}

// ---------------------------------------------------------------------------
// Kernel 3: out[b,n,:] = normalize( h[n,:] + g[b,n]*prelu(UV[n,:] + sW[b,:]) )
// One warp per (b,n) row; 8 n per block; sW+gate staged in smem with
// double-buffered prefetch; streaming stores.
// grid = (8 n-tiles, B/TB3), block = 256
// ---------------------------------------------------------------------------
__device__ __forceinline__ void row_step(const float4 uv, const float4 hh,
                                         const float4 sw, const float g,
                                         const float a, float4& o, float& ss)
{
    float c, t;
    c = uv.x + sw.x; c = (c >= 0.f) ? c : a * c; t = fmaf(g, c, hh.x); o.x = t; ss = fmaf(t, t, ss);
    c = uv.y + sw.y; c = (c >= 0.f) ? c : a * c; t = fmaf(g, c, hh.y); o.y = t; ss = fmaf(t, t, ss);
    c = uv.z + sw.z; c = (c >= 0.f) ? c : a * c; t = fmaf(g, c, hh.z); o.z = t; ss = fmaf(t, t, ss);
    c = uv.w + sw.w; c = (c >= 0.f) ? c : a * c; t = fmaf(g, c, hh.w); o.w = t; ss = fmaf(t, t, ss);
}

__global__ void __launch_bounds__(256) k3_main(
    const float* __restrict__ h, const float* __restrict__ a_ptr,
    float* __restrict__ out)
{
    __shared__ float4 sw[2][64];
    __shared__ float gt[2][8];

    const int tid = threadIdx.x;
    const int warp = tid >> 5;
    const int lane = tid & 31;
    const int n0 = blockIdx.x * 8;
    const int b0 = blockIdx.y * TB3;
    const float a = __ldg(a_ptr);

    const int n = n0 + warp;
    const int k0 = lane * 4;
    const int k1 = 128 + lane * 4;

    const float4 uv0 = *(const float4*)&g_UV[n * H_ + k0];
    const float4 uv1 = *(const float4*)&g_UV[n * H_ + k1];
    const float4 h0 = __ldg((const float4*)&h[n * H_ + k0]);
    const float4 h1 = __ldg((const float4*)&h[n * H_ + k1]);

    if (tid < 64) sw[0][tid] = __ldg((const float4*)&g_sW[(size_t)b0 * H_] + tid);
    else if (tid < 72) gt[0][tid - 64] = __ldg(&g_gate[b0 * N_ + n0 + (tid - 64)]);
    __syncthreads();

    for (int i = 0; i < TB3; ++i) {
        const int buf = i & 1;
        if (i + 1 < TB3) {
            const int bn = b0 + i + 1;
            if (tid < 64) sw[buf ^ 1][tid] = __ldg((const float4*)&g_sW[(size_t)bn * H_] + tid);
            else if (tid < 72) gt[buf ^ 1][tid - 64] = __ldg(&g_gate[bn * N_ + n0 + (tid - 64)]);
        }

        const float4 s0 = sw[buf][lane];
        const float4 s1 = sw[buf][lane + 32];
        const float g = gt[buf][warp];

        float4 o0, o1;
        float ss = 0.f;
        row_step(uv0, h0, s0, g, a, o0, ss);
        row_step(uv1, h1, s1, g, a, o1, ss);

#pragma unroll
        for (int offm = 16; offm > 0; offm >>= 1)
            ss += __shfl_xor_sync(0xFFFFFFFFu, ss, offm);
        const float inv = rsqrtf(ss);

        const int b = b0 + i;
        float4* op = (float4*)&out[((size_t)b * N_ + n) * H_];
        __stcs(op + lane, make_float4(o0.x * inv, o0.y * inv, o0.z * inv, o0.w * inv));
        __stcs(op + 32 + lane, make_float4(o1.x * inv, o1.y * inv, o1.z * inv, o1.w * inv));

        __syncthreads();
    }
}

// ---------------------------------------------------------------------------
extern "C" void kernel_launch(void* const* d_in, const int* in_sizes, int n_in,
                              void* d_out, int out_size)
{
    const float* s_t = (const float*)d_in[0];   // [B,H]
    const float* h   = (const float*)d_in[1];   // [1,N,H]
    const float* w   = (const float*)d_in[2];   // [1,N,H]
    const float* U   = (const float*)d_in[3];   // [H,H]
    const float* V   = (const float*)d_in[4];   // [H,H]
    const float* W   = (const float*)d_in[5];   // [H,H]
    const float* pa  = (const float*)d_in[6];   // [1]
    float* out = (float*)d_out;                 // [B,N,H]

    k12<<<320 + 2048, 256>>>(s_t, W, h, w, U, V);

    dim3 g3(N_ / 8, B_ / TB3);
    k3_main<<<g3, 256>>>(h, pa, out);
}